// round 17
// baseline (speedup 1.0000x reference)
#include <cuda_runtime.h>
#include <math.h>

#define NPTS 8192
#define NPAIRS (NPTS / 2)        // 4096
#define NBATCH 4
#define KNN 30
#define K8 8
#define TPB 1024
#define PPB 256                  // points per block
#define SUBS 4
#define SUBPAIRS (NPAIRS / SUBS) // 1024 pairs per sub-thread
#define CHUNKS (NPTS / PPB)      // 32
#define GRID (NBATCH * CHUNKS)   // 128
#define FMAXV 3.4028235e38f
#define SEGCAP 32                // buffer entries per (point, sub)

typedef unsigned long long u64;
typedef unsigned short u16;

#define F2_FMA(o,a,b,c) asm("fma.rn.f32x2 %0,%1,%2,%3;" : "=l"(o) : "l"(a),"l"(b),"l"(c))
#define F2_MUL(o,a,b)   asm("mul.rn.f32x2 %0,%1,%2;"    : "=l"(o) : "l"(a),"l"(b))
#define F2_ADD(o,a,b)   asm("add.rn.f32x2 %0,%1,%2;"    : "=l"(o) : "l"(a),"l"(b))

__device__ __forceinline__ u64 pack2(float lo, float hi) {
    u64 r; asm("mov.b64 %0,{%1,%2};" : "=l"(r) : "f"(lo), "f"(hi)); return r;
}
__device__ __forceinline__ void unpack2(u64 v, float& lo, float& hi) {
    asm("mov.b64 {%0,%1},%2;" : "=f"(lo), "=f"(hi) : "l"(v));
}

// smem layout (bytes)
#define OFF_SP   0                     // float4 spair[NPTS]            131072
#define OFF_BUF  131072                // u16 sbuf[SEGCAP][SUBS][PPB]   +65536
#define OFF_CNT  196608                // int scnt[SUBS][PPB]            +4096
#define OFF_G    200704                // float g8[SUBS][PPB]            +4096
#define SMEM_BYTES 204800

__device__ __forceinline__ void fetch_pt(const float4* sp, int j,
                                         float& px, float& py, float& pz) {
    const float4 A = sp[(j >> 1) * 2];
    const float4 B = sp[(j >> 1) * 2 + 1];
    const bool hi = j & 1;
    px = hi ? A.y : A.x;
    py = hi ? A.w : A.z;
    pz = hi ? B.y : B.x;
}

// Exact-rounding distance recompute, bitwise identical to the f32x2 path:
// fsub(sum, fmul(2,dot)) == fma(dot,-2,sum) because 2*dot is exact.
__device__ __forceinline__ float dist_of(const float4* sp, int j,
                                         float xi, float yi, float zi, float xxi) {
    const float4 A = sp[(j >> 1) * 2];
    const float4 B = sp[(j >> 1) * 2 + 1];
    const bool hi = j & 1;
    float px = hi ? A.y : A.x;
    float py = hi ? A.w : A.z;
    float pz = hi ? B.y : B.x;
    float pw = hi ? B.w : B.z;
    float dot = __fmaf_rn(zi, pz, __fmaf_rn(yi, py, __fmul_rn(xi, px)));
    return __fsub_rn(__fadd_rn(xxi, pw), __fmul_rn(2.0f, dot));
}

// Depth-2 evict-max inserts (descending sorted, [0] = max).
__device__ __forceinline__ void insert8(float (&bd)[K8], float d) {
    #pragma unroll
    for (int t = 0; t < K8; t++) {
        float below = (t < K8 - 1) ? bd[t + 1] : -FMAXV;
        bd[t] = fminf(bd[t], fmaxf(below, d));
    }
}
__device__ __forceinline__ void insert30(float (&bd)[KNN], float d) {
    #pragma unroll
    for (int t = 0; t < KNN; t++) {
        float below = (t < KNN - 1) ? bd[t + 1] : -FMAXV;
        bd[t] = fminf(bd[t], fmaxf(below, d));
    }
}

__global__ __launch_bounds__(TPB, 1) void knn_normals_kernel(
    const float* __restrict__ x, float* __restrict__ out)
{
    extern __shared__ char smem_raw[];
    float4* spair = (float4*)(smem_raw + OFF_SP);
    u16*    sbuf  = (u16*)(smem_raw + OFF_BUF);
    int*    scnt  = (int*)(smem_raw + OFF_CNT);
    float*  g8    = (float*)(smem_raw + OFF_G);

    const int tid = threadIdx.x;
    const int pid = tid & (PPB - 1);
    const int sub = tid >> 8;                 // 0..3
    const int plo = sub * SUBPAIRS;

    const int batch = blockIdx.x / CHUNKS;
    const int chunk = blockIdx.x % CHUNKS;
    const float* __restrict__ xb = x + (size_t)batch * 3 * NPTS;

    // Pair-packed smem: spair[2p]=(x0,x1,y0,y1), spair[2p+1]=(z0,z1,xx0,xx1).
    // xx rounded exactly as the reference (squares, then left-to-right sum).
    for (int p = tid; p < NPAIRS; p += TPB) {
        int j0 = 2 * p, j1 = 2 * p + 1;
        float x0 = xb[j0],            x1 = xb[j1];
        float y0 = xb[NPTS + j0],     y1 = xb[NPTS + j1];
        float z0 = xb[2 * NPTS + j0], z1 = xb[2 * NPTS + j1];
        float w0 = __fadd_rn(__fadd_rn(__fmul_rn(x0, x0), __fmul_rn(y0, y0)),
                             __fmul_rn(z0, z0));
        float w1 = __fadd_rn(__fadd_rn(__fmul_rn(x1, x1), __fmul_rn(y1, y1)),
                             __fmul_rn(z1, z1));
        spair[2 * p]     = make_float4(x0, x1, y0, y1);
        spair[2 * p + 1] = make_float4(z0, z1, w0, w1);
    }
    __syncthreads();

    const int i = chunk * PPB + pid;
    float xi, yi, zi;
    fetch_pt(spair, i, xi, yi, zi);
    const float4 Bi = spair[(i >> 1) * 2 + 1];
    const float xxi = (i & 1) ? Bi.w : Bi.z;

    const u64 xi2 = pack2(xi, xi), yi2 = pack2(yi, yi), zi2 = pack2(zi, zi);
    const u64 xxi2 = pack2(xxi, xxi), c_n2 = pack2(-2.0f, -2.0f);
    const ulonglong2* __restrict__ sp2 = (const ulonglong2*)spair;

    // ---- Pass 1: per-sub EXACT top-8 values (admission d < own 8th-smallest).
    float bd8[K8];
    #pragma unroll
    for (int t = 0; t < K8; t++) bd8[t] = FMAXV;
    float thr8 = FMAXV;

    #pragma unroll 4
    for (int pp = 0; pp < SUBPAIRS; pp++) {
        const int p = plo + pp;
        ulonglong2 P0 = sp2[2 * p];       // (x0,x1 | y0,y1)
        ulonglong2 P1 = sp2[2 * p + 1];   // (z0,z1 | xx0,xx1)
        u64 sump, mp, t1, dotp, dp;
        F2_ADD(sump, xxi2, P1.y);
        F2_MUL(mp, P0.x, xi2);
        F2_FMA(t1, P0.y, yi2, mp);
        F2_FMA(dotp, P1.x, zi2, t1);
        F2_FMA(dp, dotp, c_n2, sump);     // (xxi+xxj) - 2*dot, 1 rounding
        float d0, d1;
        unpack2(dp, d0, d1);
        if (fminf(d0, d1) < thr8) {
            if (d0 < thr8) { insert8(bd8, d0); thr8 = bd8[0]; }
            if (d1 < thr8) { insert8(bd8, d1); thr8 = bd8[0]; }
        }
    }
    g8[sub * PPB + pid] = bd8[0];         // exact per-sub 8th smallest
    scnt[sub * PPB + pid] = 0;
    __syncthreads();

    // gate = max of the four 8th-smallests: 32 elements <= gate => gate >= d30.
    const float gate = fmaxf(fmaxf(g8[pid], g8[PPB + pid]),
                             fmaxf(g8[2 * PPB + pid], g8[3 * PPB + pid]));

    // ---- Pass 2: collect all j with d <= gate into this sub's private
    // segment (ascending j by construction; deterministic, no atomics).
    int cnt = 0;
    #pragma unroll 4
    for (int pp = 0; pp < SUBPAIRS; pp++) {
        const int p = plo + pp;
        ulonglong2 P0 = sp2[2 * p];
        ulonglong2 P1 = sp2[2 * p + 1];
        u64 sump, mp, t1, dotp, dp;
        F2_ADD(sump, xxi2, P1.y);
        F2_MUL(mp, P0.x, xi2);
        F2_FMA(t1, P0.y, yi2, mp);
        F2_FMA(dotp, P1.x, zi2, t1);
        F2_FMA(dp, dotp, c_n2, sump);
        float d0, d1;
        unpack2(dp, d0, d1);
        if (fminf(d0, d1) <= gate) {
            if (d0 <= gate) {
                if (cnt < SEGCAP) sbuf[(cnt * SUBS + sub) * PPB + pid] = (u16)(2 * p);
                cnt++;
            }
            if (d1 <= gate) {
                if (cnt < SEGCAP) sbuf[(cnt * SUBS + sub) * PPB + pid] = (u16)(2 * p + 1);
                cnt++;
            }
        }
    }
    scnt[sub * PPB + pid] = cnt;
    __syncthreads();

    if (sub != 0) return;                 // owners do the epilogue

    int c4[SUBS];
    bool ovf = false;
    #pragma unroll
    for (int s = 0; s < SUBS; s++) {
        c4[s] = scnt[s * PPB + pid];
        if (c4[s] > SEGCAP) ovf = true;
    }

    double s1x = 0, s1y = 0, s1z = 0;
    double sxx2 = 0, sxy = 0, sxz = 0, syy = 0, syz = 0, szz = 0;
    #define ACC(J) do { float fx, fy, fz; fetch_pt(spair, (J), fx, fy, fz);    \
        double px = (double)fx, py = (double)fy, pz = (double)fz;              \
        s1x += px;  s1y += py;  s1z += pz;                                     \
        sxx2 += px * px; sxy += px * py; sxz += px * pz;                       \
        syy  += py * py; syz += py * pz; szz += pz * pz; } while (0)

    if (!ovf) {
        // thr = 30th smallest of buffer (buffer contains all d <= gate >= d30,
        // so it contains the full top-30 multiset).
        float bd30[KNN];
        #pragma unroll
        for (int t = 0; t < KNN; t++) bd30[t] = FMAXV;
        for (int s = 0; s < SUBS; s++)
            for (int k = 0; k < c4[s]; k++) {
                int j = (int)sbuf[(k * SUBS + s) * PPB + pid];
                float d = dist_of(spair, j, xi, yi, zi, xxi);
                if (d < bd30[0]) insert30(bd30, d);
            }
        const float thr = bd30[0];        // exact d30

        // strict: all d < thr, in ascending-j order (segments are j-ordered
        // and sub ranges are contiguous ascending).
        int m = 0;
        for (int s = 0; s < SUBS; s++)
            for (int k = 0; k < c4[s]; k++) {
                int j = (int)sbuf[(k * SUBS + s) * PPB + pid];
                float d = dist_of(spair, j, xi, yi, zi, xxi);
                if (d < thr) { ACC(j); m++; }
            }
        // ties: lowest-j first until 30 total (top_k tie-breaking).
        int need = KNN - m;               // >= 1
        for (int s = 0; s < SUBS && need > 0; s++)
            for (int k = 0; k < c4[s] && need > 0; k++) {
                int j = (int)sbuf[(k * SUBS + s) * PPB + pid];
                float d = dist_of(spair, j, xi, yi, zi, xxi);
                if (d == thr) { ACC(j); need--; }
            }
    } else {
        // Pathological overflow: fully serial exact path (deterministic).
        float bd30[KNN];
        #pragma unroll
        for (int t = 0; t < KNN; t++) bd30[t] = FMAXV;
        for (int j = 0; j < NPTS; j++) {
            float d = dist_of(spair, j, xi, yi, zi, xxi);
            if (d < bd30[0]) insert30(bd30, d);
        }
        const float thr = bd30[0];
        int m = 0;
        for (int j = 0; j < NPTS; j++) {
            float d = dist_of(spair, j, xi, yi, zi, xxi);
            if (d < thr) { ACC(j); m++; }
        }
        int need = KNN - m;
        for (int j = 0; j < NPTS && need > 0; j++) {
            float d = dist_of(spair, j, xi, yi, zi, xxi);
            if (d == thr) { ACC(j); need--; }
        }
    }
    #undef ACC

    const double invK = 1.0 / (double)KNN;
    double cx = s1x * invK, cy = s1y * invK, cz = s1z * invK;
    double a00 = sxx2 - (double)KNN * cx * cx;
    double a01 = sxy  - (double)KNN * cx * cy;
    double a02 = sxz  - (double)KNN * cx * cz;
    double a11 = syy  - (double)KNN * cy * cy;
    double a12 = syz  - (double)KNN * cy * cz;
    double a22 = szz  - (double)KNN * cz * cz;

    // ---- Smallest eigenpair of symmetric 3x3 (closed form, double) ----
    double vx = 1.0, vy = 0.0, vz = 0.0;
    double q  = (a00 + a11 + a22) / 3.0;
    double b00 = a00 - q, b11 = a11 - q, b22 = a22 - q;
    double p2 = b00 * b00 + b11 * b11 + b22 * b22
              + 2.0 * (a01 * a01 + a02 * a02 + a12 * a12);
    if (p2 > 0.0) {
        double p  = sqrt(p2 / 6.0);
        double ip = 1.0 / p;
        double c00 = b00 * ip, c11 = b11 * ip, c22 = b22 * ip;
        double c01 = a01 * ip, c02 = a02 * ip, c12 = a12 * ip;
        double detB = c00 * (c11 * c22 - c12 * c12)
                    - c01 * (c01 * c22 - c12 * c02)
                    + c02 * (c01 * c12 - c11 * c02);
        double rr = 0.5 * detB;
        rr = fmin(1.0, fmax(-1.0, rr));
        double phi = acos(rr) / 3.0;
        double lam = q + 2.0 * p * cos(phi + 2.0943951023931953); // smallest

        double m00 = a00 - lam, m11 = a11 - lam, m22 = a22 - lam;
        double u0x = a01 * a12 - a02 * m11;
        double u0y = a02 * a01 - m00 * a12;
        double u0z = m00 * m11 - a01 * a01;
        double u1x = a01 * m22 - a02 * a12;
        double u1y = a02 * a02 - m00 * m22;
        double u1z = m00 * a12 - a01 * a02;
        double u2x = m11 * m22 - a12 * a12;
        double u2y = a12 * a02 - a01 * m22;
        double u2z = a01 * a12 - m11 * a02;
        double n0 = u0x * u0x + u0y * u0y + u0z * u0z;
        double n1 = u1x * u1x + u1y * u1y + u1z * u1z;
        double nn2 = u2x * u2x + u2y * u2y + u2z * u2z;
        double bx = u0x, by = u0y, bz = u0z, bn = n0;
        if (n1 > bn)  { bx = u1x; by = u1y; bz = u1z; bn = n1; }
        if (nn2 > bn) { bx = u2x; by = u2y; bz = u2z; bn = nn2; }
        if (bn > 0.0) {
            double inv = rsqrt(bn);
            vx = bx * inv; vy = by * inv; vz = bz * inv;
        }
    }

    double dot2 = -((double)xi * vx + (double)yi * vy + (double)zi * vz);
    if (dot2 < 0.0) { vx = -vx; vy = -vy; vz = -vz; }

    float* __restrict__ ob = out + (size_t)batch * 6 * NPTS;
    ob[0 * NPTS + i] = xi;
    ob[1 * NPTS + i] = yi;
    ob[2 * NPTS + i] = zi;
    ob[3 * NPTS + i] = (float)vx;
    ob[4 * NPTS + i] = (float)vy;
    ob[5 * NPTS + i] = (float)vz;
}

extern "C" void kernel_launch(void* const* d_in, const int* in_sizes, int n_in,
                              void* d_out, int out_size)
{
    (void)in_sizes; (void)n_in; (void)out_size;
    const float* x = (const float*)d_in[0];
    float* out = (float*)d_out;

    cudaFuncSetAttribute(knn_normals_kernel,
                         cudaFuncAttributeMaxDynamicSharedMemorySize, SMEM_BYTES);
    knn_normals_kernel<<<GRID, TPB, SMEM_BYTES>>>(x, out);
}